// round 13
// baseline (speedup 1.0000x reference)
#include <cuda_runtime.h>
#include <math_constants.h>

#define NB    4
#define MSEQ  2048
#define CDIM  512
#define HNUM  8
#define DHEAD 64
#define TOPK  16
#define BH    (NB * HNUM)   // 32 head-batches
#define KSPLIT 2
#define KHALF  (MSEQ / KSPLIT)  // 1024

// ---------------- scratch (static device globals; no allocation) ----------------
__device__ float g_xp[NB * MSEQ * CDIM];     // conv+residual output (16 MB)
__device__ float g_q[BH * MSEQ * DHEAD];     // per-head Q
__device__ float g_k[BH * MSEQ * DHEAD];     // per-head K
__device__ float g_v[BH * MSEQ * DHEAD];     // per-head V
__device__ float g_attn[NB * MSEQ * CDIM];   // attention output, (n,m,c) layout
__device__ float g_pvals[BH * MSEQ * KSPLIT * TOPK];  // partial top-k vals (sorted asc)
__device__ int   g_pinds[BH * MSEQ * KSPLIT * TOPK];  // partial top-k global key idx

// ---------------- packed f32x2 helpers (FFMA2: 2x fp32 throughput, sm_103a) ----
__device__ __forceinline__ unsigned long long ffma2(unsigned long long a,
                                                    unsigned long long b,
                                                    unsigned long long c) {
    unsigned long long d;
    asm("fma.rn.f32x2 %0, %1, %2, %3;" : "=l"(d) : "l"(a), "l"(b), "l"(c));
    return d;
}
__device__ __forceinline__ unsigned long long fadd2(unsigned long long a,
                                                    unsigned long long b) {
    unsigned long long d;
    asm("add.rn.f32x2 %0, %1, %2;" : "=l"(d) : "l"(a), "l"(b));
    return d;
}
__device__ __forceinline__ unsigned long long pack2(float lo, float hi) {
    unsigned long long r;
    asm("mov.b64 %0, {%1, %2};" : "=l"(r) : "f"(lo), "f"(hi));
    return r;
}
__device__ __forceinline__ unsigned long long dup2(float a) {
    unsigned long long r;
    asm("mov.b64 %0, {%1, %1};" : "=l"(r) : "f"(a));
    return r;
}
__device__ __forceinline__ float2 unpack2(unsigned long long v) {
    float2 f;
    asm("mov.b64 {%0, %1}, %2;" : "=f"(f.x), "=f"(f.y) : "l"(v));
    return f;
}

// ---------------- K1: depthwise conv (k=3, SAME) + residual --------------------
__global__ void conv_res_kernel(const float* __restrict__ x,
                                const float* __restrict__ w,
                                const float* __restrict__ b) {
    int c = threadIdx.x;
    int m = blockIdx.x & (MSEQ - 1);
    int n = blockIdx.x >> 11;
    const float* base = x + ((size_t)(n * MSEQ + m)) * CDIM + c;
    float xc = base[0];
    float xl = (m > 0)        ? base[-CDIM] : 0.f;
    float xr = (m < MSEQ - 1) ? base[ CDIM] : 0.f;
    float w0 = w[3 * c], w1 = w[3 * c + 1], w2 = w[3 * c + 2];
    g_xp[((size_t)(n * MSEQ + m)) * CDIM + c] =
        xc + w0 * xl + w1 * xc + w2 * xr + b[c];
}

// ---------------- K2: QKV GEMM, 128x128 tiles, double-buffered -----------------
__global__ void __launch_bounds__(256) sgemm_qkv_kernel(const float* __restrict__ B,
                                                        const float* __restrict__ bias) {
    constexpr int NDIM = 3 * CDIM;
    __shared__ __align__(16) float As[2][16][128];
    __shared__ __align__(16) float Bs[2][16][128];

    int tid = threadIdx.x;
    int bm = blockIdx.y, bn = blockIdx.x;
    int rowBase = (tid >> 4) << 3;
    int colBase = (tid & 15) << 3;

    int ar = tid >> 2, ak = (tid & 3) << 2;
    int br = tid >> 5, bc = (tid & 31) << 2;

    const float* Ap = g_xp + ((size_t)(bm * 128)) * CDIM;
    const float* Bp = B + bn * 128;

    float4 a0 = *(const float4*)(Ap + (size_t)ar * CDIM + ak);
    float4 a1 = *(const float4*)(Ap + (size_t)(ar + 64) * CDIM + ak);
    float4 b0 = *(const float4*)(Bp + (size_t)br * NDIM + bc);
    float4 b1 = *(const float4*)(Bp + (size_t)(br + 8) * NDIM + bc);

    As[0][ak + 0][ar] = a0.x; As[0][ak + 1][ar] = a0.y;
    As[0][ak + 2][ar] = a0.z; As[0][ak + 3][ar] = a0.w;
    As[0][ak + 0][ar + 64] = a1.x; As[0][ak + 1][ar + 64] = a1.y;
    As[0][ak + 2][ar + 64] = a1.z; As[0][ak + 3][ar + 64] = a1.w;
    *(float4*)&Bs[0][br][bc] = b0;
    *(float4*)&Bs[0][br + 8][bc] = b1;
    __syncthreads();

    unsigned long long acc[8][4];
#pragma unroll
    for (int i = 0; i < 8; i++)
#pragma unroll
        for (int j = 0; j < 4; j++) acc[i][j] = 0ull;

#pragma unroll 1
    for (int kt = 0; kt < 31; kt++) {
        int cur = kt & 1, nxt = cur ^ 1;
        const float* Ak = Ap + (kt + 1) * 16;
        a0 = *(const float4*)(Ak + (size_t)ar * CDIM + ak);
        a1 = *(const float4*)(Ak + (size_t)(ar + 64) * CDIM + ak);
        const float* Bk = Bp + (size_t)((kt + 1) * 16) * NDIM;
        b0 = *(const float4*)(Bk + (size_t)br * NDIM + bc);
        b1 = *(const float4*)(Bk + (size_t)(br + 8) * NDIM + bc);

#pragma unroll
        for (int k = 0; k < 16; k++) {
            float4 av0 = *(const float4*)&As[cur][k][rowBase];
            float4 av1 = *(const float4*)&As[cur][k][rowBase + 4];
            ulonglong2 bv0 = *(const ulonglong2*)&Bs[cur][k][colBase];
            ulonglong2 bv1 = *(const ulonglong2*)&Bs[cur][k][colBase + 4];
            float af[8] = {av0.x, av0.y, av0.z, av0.w, av1.x, av1.y, av1.z, av1.w};
#pragma unroll
            for (int i = 0; i < 8; i++) {
                unsigned long long aa = dup2(af[i]);
                acc[i][0] = ffma2(aa, bv0.x, acc[i][0]);
                acc[i][1] = ffma2(aa, bv0.y, acc[i][1]);
                acc[i][2] = ffma2(aa, bv1.x, acc[i][2]);
                acc[i][3] = ffma2(aa, bv1.y, acc[i][3]);
            }
        }
        As[nxt][ak + 0][ar] = a0.x; As[nxt][ak + 1][ar] = a0.y;
        As[nxt][ak + 2][ar] = a0.z; As[nxt][ak + 3][ar] = a0.w;
        As[nxt][ak + 0][ar + 64] = a1.x; As[nxt][ak + 1][ar + 64] = a1.y;
        As[nxt][ak + 2][ar + 64] = a1.z; As[nxt][ak + 3][ar + 64] = a1.w;
        *(float4*)&Bs[nxt][br][bc] = b0;
        *(float4*)&Bs[nxt][br + 8][bc] = b1;
        __syncthreads();
    }
#pragma unroll
    for (int k = 0; k < 16; k++) {
        float4 av0 = *(const float4*)&As[1][k][rowBase];
        float4 av1 = *(const float4*)&As[1][k][rowBase + 4];
        ulonglong2 bv0 = *(const ulonglong2*)&Bs[1][k][colBase];
        ulonglong2 bv1 = *(const ulonglong2*)&Bs[1][k][colBase + 4];
        float af[8] = {av0.x, av0.y, av0.z, av0.w, av1.x, av1.y, av1.z, av1.w};
#pragma unroll
        for (int i = 0; i < 8; i++) {
            unsigned long long aa = dup2(af[i]);
            acc[i][0] = ffma2(aa, bv0.x, acc[i][0]);
            acc[i][1] = ffma2(aa, bv0.y, acc[i][1]);
            acc[i][2] = ffma2(aa, bv1.x, acc[i][2]);
            acc[i][3] = ffma2(aa, bv1.y, acc[i][3]);
        }
    }

    int co0 = bn * 128 + colBase;
    float bv[8];
#pragma unroll
    for (int j = 0; j < 8; j++) bv[j] = bias[co0 + j];

    int sec = co0 >> 9;            // 0:q 1:k 2:v
    int c2 = co0 & 511;
    int h = c2 >> 6, dd = c2 & 63;
    float* dstbuf = (sec == 0) ? g_q : (sec == 1) ? g_k : g_v;
#pragma unroll
    for (int i = 0; i < 8; i++) {
        int r = bm * 128 + rowBase + i;
        int n = r >> 11, mm = r & 2047;
        float* dst = dstbuf + ((size_t)((n * HNUM + h) * MSEQ + mm)) * DHEAD + dd;
        float2 p0 = unpack2(acc[i][0]), p1 = unpack2(acc[i][1]);
        float2 p2 = unpack2(acc[i][2]), p3 = unpack2(acc[i][3]);
        *(float4*)dst = make_float4(p0.x + bv[0], p0.y + bv[1],
                                    p1.x + bv[2], p1.y + bv[3]);
        *(float4*)(dst + 4) = make_float4(p2.x + bv[4], p2.y + bv[5],
                                          p3.x + bv[6], p3.y + bv[7]);
    }
}

// ---------------- sorted top-16 parallel shift-insert --------------------------
// vals ascending; vals[0] is the running 16th-largest. Strict '<' keeps earlier
// (lower-index) keys on ties, matching lax.top_k.
__device__ __forceinline__ void topk_insert(float (&vals)[TOPK], int (&inds)[TOPK],
                                            float s, int key) {
    bool c[TOPK];
#pragma unroll
    for (int t = 0; t < TOPK; t++) c[t] = vals[t] < s;
#pragma unroll
    for (int t = 0; t < TOPK - 1; t++) {
        vals[t] = c[t + 1] ? vals[t + 1] : (c[t] ? s : vals[t]);
        inds[t] = c[t + 1] ? inds[t + 1] : (c[t] ? key : inds[t]);
    }
    vals[TOPK - 1] = c[TOPK - 1] ? s : vals[TOPK - 1];
    inds[TOPK - 1] = c[TOPK - 1] ? key : inds[TOPK - 1];
}

// ---------------- K3a: routing logits + partial top-16 (split-K over keys) -----
// TWO queries per thread: every broadcast key LDS.128 now feeds 2 queries, so
// the hot loop runs at FFMA2:LDS = 4:1 (vs 2:1 in rounds 6-12) - the FFMA2 pipe
// is the single binding resource with 2x slack for LDS and bookkeeping.
// 16 independent accumulator chains (2q x 4keys, revisit distance 16 ops) keep
// the pipe fed at 2 warps/SMSP. Exact divergent insert (R11 style - proven
// cheaper than the branchless stack in R12).
__global__ void __launch_bounds__(128, 2) route_part_kernel() {
    __shared__ __align__(16) float ks[64 * DHEAD];   // 16 KB key tile

    int bx = blockIdx.x;
    int b   = bx >> 4;          // head-batch 0..31  (16 blocks per bh)
    int ksp = (bx >> 3) & 1;    // key split 0/1
    int qt  = bx & 7;           // query tile (256 queries each)
    int tid = threadIdx.x;
    int m0 = qt * 256 + tid;    // query A
    int m1 = m0 + 128;          // query B

    const float scale = 0.04419417382415922f;        // 512^-0.5

    const float* qrow0 = g_q + ((size_t)(b * MSEQ + m0)) * DHEAD;
    const float* qrow1 = g_q + ((size_t)(b * MSEQ + m1)) * DHEAD;
    unsigned long long qp0[32], qp1[32];
#pragma unroll
    for (int d4 = 0; d4 < 16; d4++) {
        float4 t = ((const float4*)qrow0)[d4];
        qp0[2 * d4]     = pack2(t.x * scale, t.y * scale);
        qp0[2 * d4 + 1] = pack2(t.z * scale, t.w * scale);
        float4 u = ((const float4*)qrow1)[d4];
        qp1[2 * d4]     = pack2(u.x * scale, u.y * scale);
        qp1[2 * d4 + 1] = pack2(u.z * scale, u.w * scale);
    }

    float vals0[TOPK], vals1[TOPK];
    int   inds0[TOPK], inds1[TOPK];
#pragma unroll
    for (int t = 0; t < TOPK; t++) {
        vals0[t] = -CUDART_INF_F; inds0[t] = 0;
        vals1[t] = -CUDART_INF_F; inds1[t] = 0;
    }

    const float* kbase = g_k + (size_t)b * MSEQ * DHEAD + (size_t)ksp * KHALF * DHEAD;

    for (int kt = 0; kt < KHALF / 64; kt++) {
        const float4* src = (const float4*)(kbase + (size_t)kt * 64 * DHEAD);
#pragma unroll
        for (int u = 0; u < 8; u++)
            ((float4*)ks)[tid + u * 128] = src[tid + u * 128];
        __syncthreads();

#pragma unroll 1
        for (int j = 0; j < 64; j += 4) {
            const ulonglong2* kr0 = (const ulonglong2*)(ks + (j + 0) * DHEAD);
            const ulonglong2* kr1 = (const ulonglong2*)(ks + (j + 1) * DHEAD);
            const ulonglong2* kr2 = (const ulonglong2*)(ks + (j + 2) * DHEAD);
            const ulonglong2* kr3 = (const ulonglong2*)(ks + (j + 3) * DHEAD);
            unsigned long long A0 = 0ull, A1 = 0ull, A2 = 0ull, A3 = 0ull;
            unsigned long long B0 = 0ull, B1 = 0ull, B2 = 0ull, B3 = 0ull;
            // per pc: 4 broadcast LDS.128 feed 16 FFMA2-pairs (2 queries)
#pragma unroll
            for (int pc = 0; pc < 16; pc++) {
                ulonglong2 k0 = kr0[pc], k1 = kr1[pc], k2 = kr2[pc], k3 = kr3[pc];
                unsigned long long qa = qp0[2 * pc], qb = qp0[2 * pc + 1];
                unsigned long long ra = qp1[2 * pc], rb = qp1[2 * pc + 1];
                A0 = ffma2(qa, k0.x, A0); A1 = ffma2(qa, k1.x, A1);
                A2 = ffma2(qa, k2.x, A2); A3 = ffma2(qa, k3.x, A3);
                B0 = ffma2(ra, k0.x, B0); B1 = ffma2(ra, k1.x, B1);
                B2 = ffma2(ra, k2.x, B2); B3 = ffma2(ra, k3.x, B3);
                A0 = ffma2(qb, k0.y, A0); A1 = ffma2(qb, k1.y, A1);
                A2 = ffma2(qb, k2.y, A2); A3 = ffma2(qb, k3.y, A3);
                B0 = ffma2(rb, k0.y, B0); B1 = ffma2(rb, k1.y, B1);
                B2 = ffma2(rb, k2.y, B2); B3 = ffma2(rb, k3.y, B3);
            }
            float2 fa0 = unpack2(A0), fa1 = unpack2(A1);
            float2 fa2 = unpack2(A2), fa3 = unpack2(A3);
            float2 fb0 = unpack2(B0), fb1 = unpack2(B1);
            float2 fb2 = unpack2(B2), fb3 = unpack2(B3);
            float s00 = fa0.x + fa0.y, s01 = fa1.x + fa1.y;
            float s02 = fa2.x + fa2.y, s03 = fa3.x + fa3.y;
            float s10 = fb0.x + fb0.y, s11 = fb1.x + fb1.y;
            float s12 = fb2.x + fb2.y, s13 = fb3.x + fb3.y;
            int key = kt * 64 + j;

            float t0 = fmaxf(fmaxf(s00, s01), fmaxf(s02, s03));
            if (t0 > vals0[0]) {
                if (s00 > vals0[0]) topk_insert(vals0, inds0, s00, key);
                if (s01 > vals0[0]) topk_insert(vals0, inds0, s01, key + 1);
                if (s02 > vals0[0]) topk_insert(vals0, inds0, s02, key + 2);
                if (s03 > vals0[0]) topk_insert(vals0, inds0, s03, key + 3);
            }
            float t1 = fmaxf(fmaxf(s10, s11), fmaxf(s12, s13));
            if (t1 > vals1[0]) {
                if (s10 > vals1[0]) topk_insert(vals1, inds1, s10, key);
                if (s11 > vals1[0]) topk_insert(vals1, inds1, s11, key + 1);
                if (s12 > vals1[0]) topk_insert(vals1, inds1, s12, key + 2);
                if (s13 > vals1[0]) topk_insert(vals1, inds1, s13, key + 3);
            }
        }
        __syncthreads();
    }

    int koff = ksp * KHALF;
    size_t base0 = ((size_t)(b * MSEQ + m0) * KSPLIT + ksp) * TOPK;
    size_t base1 = ((size_t)(b * MSEQ + m1) * KSPLIT + ksp) * TOPK;
#pragma unroll
    for (int t = 0; t < TOPK; t++) {
        g_pvals[base0 + t] = vals0[t];
        g_pinds[base0 + t] = inds0[t] + koff;
        g_pvals[base1 + t] = vals1[t];
        g_pinds[base1 + t] = inds1[t] + koff;
    }
}

// ---------------- K3b: merge partial top-16s + softmax + V gather --------------
// 4 threads per query; redundant merge/softmax, split V gather (16 dims/thread).
__global__ void __launch_bounds__(256) merge_attn_kernel() {
    int tid = threadIdx.x;
    int qloc = tid >> 2, sub = tid & 3;
    int g = blockIdx.x * 64 + qloc;              // global query 0..65535
    int b = g >> 11, m = g & 2047;

    size_t base = (size_t)g * (KSPLIT * TOPK);
    float vals[TOPK];
    int   inds[TOPK];
#pragma unroll
    for (int i = 0; i < 4; i++) {                // split 0, sorted ascending
        float4 v = ((const float4*)(g_pvals + base))[i];
        int4   x = ((const int4*)(g_pinds + base))[i];
        vals[4 * i + 0] = v.x; vals[4 * i + 1] = v.y;
        vals[4 * i + 2] = v.z; vals[4 * i + 3] = v.w;
        inds[4 * i + 0] = x.x; inds[4 * i + 1] = x.y;
        inds[4 * i + 2] = x.z; inds[4 * i + 3] = x.w;
    }
#pragma unroll
    for (int i = 0; i < 4; i++) {                // insert split 1
        float4 v = ((const float4*)(g_pvals + base + TOPK))[i];
        int4   x = ((const int4*)(g_pinds + base + TOPK))[i];
        topk_insert(vals, inds, v.x, x.x);
        topk_insert(vals, inds, v.y, x.y);
        topk_insert(vals, inds, v.z, x.z);
        topk_insert(vals, inds, v.w, x.w);
    }

    float mx = vals[TOPK - 1];                   // sorted: last is max
    float w[TOPK];
    float sum = 0.f;
#pragma unroll
    for (int t = 0; t < TOPK; t++) { w[t] = expf(vals[t] - mx); sum += w[t]; }
    float inv = 1.f / sum;

    unsigned long long o[8];
#pragma unroll
    for (int p = 0; p < 8; p++) o[p] = 0ull;

    const float* vbase = g_v + (size_t)b * MSEQ * DHEAD + sub * 16;
#pragma unroll
    for (int t = 0; t < TOPK; t++) {
        unsigned long long wt = dup2(w[t] * inv);
        const ulonglong2* vr = (const ulonglong2*)(vbase + (size_t)inds[t] * DHEAD);
#pragma unroll
        for (int p = 0; p < 4; p++) {
            ulonglong2 vv = vr[p];
            o[2 * p]     = ffma2(wt, vv.x, o[2 * p]);
            o[2 * p + 1] = ffma2(wt, vv.y, o[2 * p + 1]);
        }
    }

    int n = b >> 3, h = b & 7;
    float* dst = g_attn + ((size_t)(n * MSEQ + m)) * CDIM + h * DHEAD + sub * 16;
#pragma unroll
    for (int p = 0; p < 4; p++) {
        ulonglong2 wv; wv.x = o[2 * p]; wv.y = o[2 * p + 1];
        ((ulonglong2*)dst)[p] = wv;
    }
}

// ---------------- K4: output GEMM, 64x128 tiles, double-buffered ---------------
__global__ void __launch_bounds__(256) sgemm_out_kernel(const float* __restrict__ B,
                                                        const float* __restrict__ bias,
                                                        float* __restrict__ Cout) {
    constexpr int NDIM = CDIM;
    __shared__ __align__(16) float As[2][16][64];
    __shared__ __align__(16) float Bs[2][16][128];

    int tid = threadIdx.x;
    int bm = blockIdx.y, bn = blockIdx.x;
    int rowBase = (tid >> 4) << 2;
    int colBase = (tid & 15) << 3;

    int ar = tid >> 2, ak = (tid & 3) << 2;
    int br = tid >> 5, bc = (tid & 31) << 2;

    const float* Ap = g_attn + ((size_t)(bm * 64)) * CDIM;
    const float* Bp = B + bn * 128;

    float4 a0 = *(const float4*)(Ap + (size_t)ar * CDIM + ak);
    float4 b0 = *(const float4*)(Bp + (size_t)br * NDIM + bc);
    float4 b1 = *(const float4*)(Bp + (size_t)(br + 8) * NDIM + bc);
    As[0][ak + 0][ar] = a0.x; As[0][ak + 1][ar] = a0.y;
    As[0][ak + 2][ar] = a0.z; As[0][ak + 3][ar] = a0.w;
    *(float4*)&Bs[0][br][bc] = b0;
    *(float4*)&Bs[0][br + 8][bc] = b1;
    __syncthreads();

    unsigned long long acc[4][4];
#pragma unroll
    for (int i = 0; i < 4; i++)
#pragma unroll
        for (int j = 0; j < 4; j++) acc[i][j] = 0ull;

#pragma unroll 1
    for (int kt = 0; kt < 31; kt++) {
        int cur = kt & 1, nxt = cur ^ 1;
        const float* Ak = Ap + (kt + 1) * 16;
        a0 = *(const float4*)(Ak + (size_t)ar * CDIM + ak);
        const float* Bk = Bp + (size_t)((kt + 1) * 16) * NDIM;
        b0 = *(const float4*)(Bk + (size_t)br * NDIM + bc);
        b1 = *(const float4*)(Bk + (size_t)(br + 8) * NDIM + bc);

#pragma unroll
        for (int k = 0; k < 16; k++) {
            float4 av = *(const float4*)&As[cur][k][rowBase];
            ulonglong2 bv0 = *(const ulonglong2*)&Bs[cur][k][colBase];
            ulonglong2 bv1 = *(const ulonglong2*)&Bs[cur][k][colBase + 4];
            float af[4] = {av.x, av.y, av.z, av.w};
#pragma unroll
            for (int i = 0; i < 4; i++) {
                unsigned long long aa = dup2(af[i]);
                acc[i][0] = ffma2(aa, bv0.x, acc[i][0]);
                acc[i][1] = ffma2(aa, bv0.y, acc[i][1]);
                acc[i][2] = ffma2(aa, bv1.x, acc[i][2]);
                acc[i][3] = ffma2(aa, bv1.y, acc[i][3]);
            }
        }
        As[nxt][ak + 0][ar] = a0.x; As[nxt][ak + 1][ar] = a0.y;
        As[nxt][ak + 2][ar] = a0.z; As[nxt][ak + 3][ar] = a0.w;
        *(float4*)&Bs[nxt][br][bc] = b0;
        *(float4*)&Bs[nxt][br + 8][bc] = b1;
        __syncthreads();
    }
#pragma unroll
    for (int k = 0; k < 16; k++) {
        float4 av = *(const float4*)&As[1][k][rowBase];
        ulonglong2 bv0 = *(const ulonglong2*)&Bs[1][k][colBase];
        ulonglong2 bv1 = *(const ulonglong2*)&Bs[1][k][colBase + 4];
        float af[4] = {av.x, av.y, av.z, av.w};
#pragma unroll
        for (int i = 0; i < 4; i++) {
            unsigned long long aa = dup2(af[i]);
            acc[i][0] = ffma2(aa, bv0.x, acc[i][0]);
            acc[i][1] = ffma2(aa, bv0.y, acc[i][1]);
            acc[i][2] = ffma2(aa, bv1.x, acc[i][2]);
            acc[i][3] = ffma2(aa, bv1.y, acc[i][3]);
        }
    }

    int co0 = bn * 128 + colBase;
    float bv[8];
#pragma unroll
    for (int j = 0; j < 8; j++) bv[j] = bias[co0 + j];
#pragma unroll
    for (int i = 0; i < 4; i++) {
        int r = bm * 64 + rowBase + i;
        float* dst = Cout + (size_t)r * NDIM + co0;
        float2 p0 = unpack2(acc[i][0]), p1 = unpack2(acc[i][1]);
        float2 p2 = unpack2(acc[i][2]), p3 = unpack2(acc[i][3]);
        *(float4*)dst = make_float4(p0.x + bv[0], p0.y + bv[1],
                                    p1.x + bv[2], p1.y + bv[3]);
        *(float4*)(dst + 4) = make_float4(p2.x + bv[4], p2.y + bv[5],
                                          p3.x + bv[6], p3.y + bv[7]);
    }
}

// ---------------- launch ----------------
extern "C" void kernel_launch(void* const* d_in, const int* in_sizes, int n_in,
                              void* d_out, int out_size) {
    (void)in_sizes; (void)n_in; (void)out_size;
    const float* x      = (const float*)d_in[0];
    const float* conv_w = (const float*)d_in[1];
    const float* conv_b = (const float*)d_in[2];
    const float* w_qkv  = (const float*)d_in[3];
    const float* b_qkv  = (const float*)d_in[4];
    const float* w_o    = (const float*)d_in[5];
    const float* b_o    = (const float*)d_in[6];

    conv_res_kernel<<<NB * MSEQ, CDIM>>>(x, conv_w, conv_b);
    sgemm_qkv_kernel<<<dim3(12, 64), 256>>>(w_qkv, b_qkv);
    route_part_kernel<<<BH * 8 * KSPLIT, 128>>>();
    merge_attn_kernel<<<1024, 256>>>();
    sgemm_out_kernel<<<dim3(4, 128), 256>>>(w_o, b_o, (float*)d_out);
}